// round 5
// baseline (speedup 1.0000x reference)
#include <cuda_runtime.h>

// CenterLoss collapses algebraically: after masking, only the true-label
// column survives; the other C-1 zeros clamp to 1e-12 each.
//   loss = sum_n clamp(||x_n - c_{lab_n}||^2, 1e-12, 1e12) + N*(C-1)*1e-12
//
// R5 layout: one row per WARP. 512 CTAs x 256 threads = 4096 warps (occ ~45%).
// Each lane front-loads 4 float4 from x and 4 from the gathered center into
// register arrays BEFORE computing (forces ptxas to batch 8 LDG.128 -> MLP=8),
// then squared-diff dot + warp reduce. Last CTA (atomic counter over 512)
// does a fixed-order final reduction -> bitwise deterministic.

#define N_ROWS 4096      // 16 * 256
#define FEAT_DIM 512
#define F4_PER_ROW (FEAT_DIM / 4)   // 128
#define NUM_CLASSES 10000
#define NUM_CTAS 512
#define WARPS_PER_CTA 8
#define ROWS_PER_CTA WARPS_PER_CTA   // one row per warp

__device__ float g_cta_partials[NUM_CTAS];
__device__ unsigned int g_done_count = 0;

__global__ __launch_bounds__(256) void center_loss_kernel(
    const float* __restrict__ x,
    const int* __restrict__ labels,
    const float* __restrict__ centers,
    float* __restrict__ out)
{
    const int t = threadIdx.x;
    const int warp = t >> 5;
    const int lane = t & 31;
    const int cta = blockIdx.x;
    const int row = cta * ROWS_PER_CTA + warp;

    __shared__ int s_lab[ROWS_PER_CTA];
    __shared__ float s_warp[WARPS_PER_CTA];
    __shared__ bool s_is_last;

    if (t < ROWS_PER_CTA) {
        int c = labels[cta * ROWS_PER_CTA + t];
        s_lab[t] = min(max(c, 0), NUM_CLASSES - 1);
    }
    __syncthreads();

    const int cidx = s_lab[warp];

    const float4* __restrict__ xr =
        reinterpret_cast<const float4*>(x) + (size_t)row * F4_PER_ROW;
    const float4* __restrict__ cr =
        reinterpret_cast<const float4*>(centers) + (size_t)cidx * F4_PER_ROW;

    // Front-batch all 8 LDG.128s (4 from x, 4 from center) before any math.
    float4 a[4], b[4];
    #pragma unroll
    for (int i = 0; i < 4; i++) a[i] = xr[i * 32 + lane];
    #pragma unroll
    for (int i = 0; i < 4; i++) b[i] = cr[i * 32 + lane];

    float s = 0.0f;
    #pragma unroll
    for (int i = 0; i < 4; i++) {
        float d0 = a[i].x - b[i].x;
        float d1 = a[i].y - b[i].y;
        float d2 = a[i].z - b[i].z;
        float d3 = a[i].w - b[i].w;
        s += d0 * d0 + d1 * d1 + d2 * d2 + d3 * d3;
    }

    // warp reduce
    #pragma unroll
    for (int o = 16; o > 0; o >>= 1)
        s += __shfl_xor_sync(0xffffffffu, s, o);

    if (lane == 0) {
        // per-row clamp (identity in practice: dist ~ 1000)
        s_warp[warp] = fminf(fmaxf(s, 1e-12f), 1e12f);
    }
    __syncthreads();

    if (t == 0) {
        float tot = 0.0f;
        #pragma unroll
        for (int w = 0; w < WARPS_PER_CTA; w++) tot += s_warp[w];
        g_cta_partials[cta] = tot;
        __threadfence();
        unsigned int v = atomicAdd(&g_done_count, 1u);
        s_is_last = (v == (unsigned int)(NUM_CTAS - 1));
    }
    __syncthreads();

    if (s_is_last) {
        // 512 partials: each of the 256 threads sums 2 in fixed order.
        float v = g_cta_partials[t] + g_cta_partials[t + 256];

        #pragma unroll
        for (int o = 16; o > 0; o >>= 1)
            v += __shfl_xor_sync(0xffffffffu, v, o);

        __shared__ float fs[WARPS_PER_CTA];
        if (lane == 0) fs[warp] = v;
        __syncthreads();

        if (t == 0) {
            const float zero_clamp_sum =
                (float)((double)N_ROWS * (double)(NUM_CLASSES - 1) * 1e-12);
            float r = 0.0f;
            #pragma unroll
            for (int w = 0; w < WARPS_PER_CTA; w++) r += fs[w];
            out[0] = r + zero_clamp_sum;
            g_done_count = 0;   // reset for next graph replay
        }
    }
}

extern "C" void kernel_launch(void* const* d_in, const int* in_sizes, int n_in,
                              void* d_out, int out_size)
{
    const float* x       = (const float*)d_in[0];  // (16,256,512) f32
    const int*   labels  = (const int*)d_in[1];    // (16,256) int32
    const float* centers = (const float*)d_in[2];  // (10000,512) f32
    float*       out     = (float*)d_out;          // scalar

    (void)in_sizes; (void)n_in; (void)out_size;

    center_loss_kernel<<<NUM_CTAS, 256>>>(x, labels, centers, out);
}

// round 6
// speedup vs baseline: 1.0778x; 1.0778x over previous
#include <cuda_runtime.h>

// CenterLoss collapses algebraically: after masking, only the true-label
// column survives; the other C-1 zeros clamp to 1e-12 each.
//   loss = sum_n clamp(||x_n - c_{lab_n}||^2, 1e-12, 1e12) + N*(C-1)*1e-12
//
// R6: occupancy-first. 1024 CTAs x 256 threads (=262K threads, single wave,
// 100% warp-slot occupancy at 8 CTAs/SM via launch_bounds reg cap). Each CTA
// owns 4 rows; warp w covers half-row (row w>>1, half w&1) with 2 float4
// loads per lane per operand (MLP 4). Half sums combined in smem so the
// per-row clamp is preserved. Fused last-CTA tail over 1024 partials,
// fixed-order everywhere -> deterministic.

#define N_ROWS 4096      // 16 * 256
#define FEAT_DIM 512
#define F4_PER_ROW (FEAT_DIM / 4)   // 128
#define NUM_CLASSES 10000
#define NUM_CTAS 1024
#define ROWS_PER_CTA 4

__device__ float g_cta_partials[NUM_CTAS];
__device__ unsigned int g_done_count = 0;

__global__ __launch_bounds__(256, 8) void center_loss_kernel(
    const float* __restrict__ x,
    const int* __restrict__ labels,
    const float* __restrict__ centers,
    float* __restrict__ out)
{
    const int t = threadIdx.x;
    const int warp = t >> 5;          // 0..7
    const int lane = t & 31;
    const int cta = blockIdx.x;
    const int lrow = warp >> 1;       // 0..3 local row
    const int half = warp & 1;        // 0..1 half of the row

    __shared__ int s_lab[ROWS_PER_CTA];
    __shared__ float s_half[8];
    __shared__ bool s_is_last;

    if (t < ROWS_PER_CTA) {
        int c = labels[cta * ROWS_PER_CTA + t];
        s_lab[t] = min(max(c, 0), NUM_CLASSES - 1);
    }
    __syncthreads();

    const int row = cta * ROWS_PER_CTA + lrow;
    const int cidx = s_lab[lrow];

    const float4* __restrict__ xr =
        reinterpret_cast<const float4*>(x) + (size_t)row * F4_PER_ROW + half * 64;
    const float4* __restrict__ cr =
        reinterpret_cast<const float4*>(centers) + (size_t)cidx * F4_PER_ROW + half * 64;

    // 2 float4 per operand per lane -> 4 outstanding LDG.128
    float4 a0 = xr[lane];
    float4 b0 = cr[lane];
    float4 a1 = xr[32 + lane];
    float4 b1 = cr[32 + lane];

    float d0 = a0.x - b0.x, d1 = a0.y - b0.y, d2 = a0.z - b0.z, d3 = a0.w - b0.w;
    float s = d0 * d0 + d1 * d1 + d2 * d2 + d3 * d3;
    d0 = a1.x - b1.x; d1 = a1.y - b1.y; d2 = a1.z - b1.z; d3 = a1.w - b1.w;
    s += d0 * d0 + d1 * d1 + d2 * d2 + d3 * d3;

    // warp reduce -> lane 0 holds half-row sum
    #pragma unroll
    for (int o = 16; o > 0; o >>= 1)
        s += __shfl_xor_sync(0xffffffffu, s, o);

    if (lane == 0) s_half[warp] = s;
    __syncthreads();

    if (t == 0) {
        float acc = 0.0f;
        #pragma unroll
        for (int r = 0; r < ROWS_PER_CTA; r++) {
            float rs = s_half[2 * r] + s_half[2 * r + 1];
            rs = fminf(fmaxf(rs, 1e-12f), 1e12f);   // per-row clamp
            acc += rs;
        }
        g_cta_partials[cta] = acc;
        __threadfence();
        unsigned int v = atomicAdd(&g_done_count, 1u);
        s_is_last = (v == (unsigned int)(NUM_CTAS - 1));
    }
    __syncthreads();

    if (s_is_last) {
        // 1024 partials: each thread sums 4 in fixed index order.
        float v = 0.0f;
        #pragma unroll
        for (int i = 0; i < 4; i++)
            v += g_cta_partials[t + 256 * i];

        #pragma unroll
        for (int o = 16; o > 0; o >>= 1)
            v += __shfl_xor_sync(0xffffffffu, v, o);

        __shared__ float fs[8];
        if (lane == 0) fs[warp] = v;
        __syncthreads();

        if (t == 0) {
            const float zero_clamp_sum =
                (float)((double)N_ROWS * (double)(NUM_CLASSES - 1) * 1e-12);
            float r = 0.0f;
            #pragma unroll
            for (int w = 0; w < 8; w++) r += fs[w];
            out[0] = r + zero_clamp_sum;
            g_done_count = 0;   // reset for next graph replay
        }
    }
}

extern "C" void kernel_launch(void* const* d_in, const int* in_sizes, int n_in,
                              void* d_out, int out_size)
{
    const float* x       = (const float*)d_in[0];  // (16,256,512) f32
    const int*   labels  = (const int*)d_in[1];    // (16,256) int32
    const float* centers = (const float*)d_in[2];  // (10000,512) f32
    float*       out     = (float*)d_out;          // scalar

    (void)in_sizes; (void)n_in; (void)out_size;

    center_loss_kernel<<<NUM_CTAS, 256>>>(x, labels, centers, out);
}